// round 5
// baseline (speedup 1.0000x reference)
#include <cuda_runtime.h>
#include <cuda_bf16.h>
#include <math.h>

// ---------------- Problem constants ----------------
#define BB 2
#define TT 4
#define NN 1024
#define MM 256
#define KK 32
#define CC 512
#define HH 8
#define DH 64
#define MTOK 1024
#define MLPD 2048
#define NBH 16

// ---------------- Scratch ----------------
__device__ float g_anchor[BB * TT * MM * 3];
__device__ int   g_bq[BB * TT * 3 * MM * KK];
__device__ float g_feats[BB * MTOK * CC];
__device__ float g_xln[BB * MTOK * CC];
__device__ float g_qkv[BB * MTOK * 3 * CC];
__device__ float g_q[NBH * MTOK * DH];
__device__ float g_k[NBH * MTOK * DH];
__device__ float g_v[NBH * MTOK * DH];
__device__ float g_ov[NBH * MTOK * DH];
__device__ float g_attn[(size_t)NBH * MTOK * MTOK];
__device__ float g_axyz[NBH * MTOK * 3];
__device__ float g_attnout[BB * MTOK * CC];
__device__ float g_hid[BB * MTOK * MLPD];

// ---------------- FPS ----------------
__global__ void fps_kernel(const float* __restrict__ xyzs) {
    int b = blockIdx.x >> 2, t = blockIdx.x & 3;
    const float* fr = xyzs + (size_t)(b * TT + t) * NN * 3;
    int tid = threadIdx.x, lane = tid & 31, wrp = tid >> 5;
    __shared__ float wv[32];
    __shared__ int wi[32];
    __shared__ int s_last;
    float px = fr[tid * 3 + 0], py = fr[tid * 3 + 1], pz = fr[tid * 3 + 2];
    float dist = 1e10f;
    int aoff = (b * TT + t) * MM;
    if (tid == 0) {
        g_anchor[(size_t)aoff * 3 + 0] = fr[0];
        g_anchor[(size_t)aoff * 3 + 1] = fr[1];
        g_anchor[(size_t)aoff * 3 + 2] = fr[2];
        s_last = 0;
    }
    __syncthreads();
    for (int it = 1; it < MM; ++it) {
        int last = s_last;
        float lx = fr[last * 3 + 0], ly = fr[last * 3 + 1], lz = fr[last * 3 + 2];
        float dx = px - lx, dy = py - ly, dz = pz - lz;
        float d = __fadd_rn(__fadd_rn(__fmul_rn(dx, dx), __fmul_rn(dy, dy)),
                            __fmul_rn(dz, dz));
        dist = fminf(dist, d);
        float bv = dist; int bi = tid;
        #pragma unroll
        for (int o = 16; o; o >>= 1) {
            float ov = __shfl_xor_sync(0xffffffffu, bv, o);
            int   oi = __shfl_xor_sync(0xffffffffu, bi, o);
            if (ov > bv || (ov == bv && oi < bi)) { bv = ov; bi = oi; }
        }
        if (lane == 0) { wv[wrp] = bv; wi[wrp] = bi; }
        __syncthreads();
        if (tid < 32) {
            bv = wv[tid]; bi = wi[tid];
            #pragma unroll
            for (int o = 16; o; o >>= 1) {
                float ov = __shfl_xor_sync(0xffffffffu, bv, o);
                int   oi = __shfl_xor_sync(0xffffffffu, bi, o);
                if (ov > bv || (ov == bv && oi < bi)) { bv = ov; bi = oi; }
            }
            if (tid == 0) {
                s_last = bi;
                g_anchor[((size_t)(aoff + it)) * 3 + 0] = fr[bi * 3 + 0];
                g_anchor[((size_t)(aoff + it)) * 3 + 1] = fr[bi * 3 + 1];
                g_anchor[((size_t)(aoff + it)) * 3 + 2] = fr[bi * 3 + 2];
            }
        }
        __syncthreads();
    }
}

// ---------------- Ball query ----------------
__global__ void ballq_kernel(const float* __restrict__ xyzs) {
    int gid = blockIdx.x * blockDim.x + threadIdx.x;
    if (gid >= BB * TT * 3 * MM) return;
    int mm = gid & (MM - 1);
    int r = gid >> 8;
    int tap = r % 3; r /= 3;
    int t = r & 3;
    int b = r >> 2;
    int src = t - 1 + tap;
    src = src < 0 ? 0 : (src > 3 ? 3 : src);
    const float* nb = xyzs + (size_t)(b * TT + src) * NN * 3;
    const float* an = g_anchor + ((size_t)((b * TT + t) * MM + mm)) * 3;
    float ax = an[0], ay = an[1], az = an[2];
    int* o = g_bq + (size_t)gid * KK;
    int cnt = 0;
    for (int j = 0; j < NN && cnt < KK; ++j) {
        float dx = ax - nb[j * 3], dy = ay - nb[j * 3 + 1], dz = az - nb[j * 3 + 2];
        float d2 = __fadd_rn(__fadd_rn(__fmul_rn(dx, dx), __fmul_rn(dy, dy)),
                             __fmul_rn(dz, dz));
        if (d2 < 1.0f) o[cnt++] = j;
    }
    int fill = (cnt > 0) ? o[0] : 0;
    for (int c = cnt; c < KK; ++c) o[c] = fill;
}

// ---------------- p4dconv ----------------
__global__ void conv_kernel(const float* __restrict__ xyzs, const float* __restrict__ Wd) {
    int blk = blockIdx.x;
    int mm = blk & (MM - 1);
    int t = (blk >> 8) & 3;
    int b = blk >> 10;
    int tid = threadIdx.x;
    __shared__ float sd[96][4];
    const float* an = g_anchor + (size_t)blk * 3;
    if (tid < 96) {
        int tap = tid >> 5, k = tid & 31;
        int src = t - 1 + tap;
        src = src < 0 ? 0 : (src > 3 ? 3 : src);
        const float* nb = xyzs + (size_t)(b * TT + src) * NN * 3;
        int j = g_bq[(((size_t)(b * TT + t) * 3 + tap) * MM + mm) * KK + k];
        sd[tid][0] = nb[j * 3 + 0] - an[0];
        sd[tid][1] = nb[j * 3 + 1] - an[1];
        sd[tid][2] = nb[j * 3 + 2] - an[2];
        sd[tid][3] = (float)(tap - 1);
    }
    __syncthreads();
    float w0 = Wd[tid * 4 + 0], w1 = Wd[tid * 4 + 1],
          w2 = Wd[tid * 4 + 2], w3 = Wd[tid * 4 + 3];
    float best = -1e30f;
    #pragma unroll 4
    for (int r = 0; r < 96; ++r) {
        float v = sd[r][0] * w0 + sd[r][1] * w1 + sd[r][2] * w2 + sd[r][3] * w3;
        best = fmaxf(best, v);
    }
    g_feats[(size_t)blk * CC + tid] = fmaxf(best, 0.0f);
}

// ---------------- LayerNorm ----------------
__global__ void ln_kernel(const float* __restrict__ in, float* __restrict__ out,
                          const float* __restrict__ gg, const float* __restrict__ bb) {
    int row = blockIdx.x, tid = threadIdx.x;
    float x = in[(size_t)row * CC + tid];
    __shared__ float red[16];
    float s = x;
    #pragma unroll
    for (int o = 16; o; o >>= 1) s += __shfl_xor_sync(0xffffffffu, s, o);
    if ((tid & 31) == 0) red[tid >> 5] = s;
    __syncthreads();
    if (tid == 0) {
        float m = 0.f;
        #pragma unroll
        for (int i = 0; i < 16; i++) m += red[i];
        red[0] = m;
    }
    __syncthreads();
    float mu = red[0] * (1.0f / CC);
    float dlt = x - mu;
    __syncthreads();
    float s2 = dlt * dlt;
    #pragma unroll
    for (int o = 16; o; o >>= 1) s2 += __shfl_xor_sync(0xffffffffu, s2, o);
    if ((tid & 31) == 0) red[tid >> 5] = s2;
    __syncthreads();
    if (tid == 0) {
        float m = 0.f;
        #pragma unroll
        for (int i = 0; i < 16; i++) m += red[i];
        red[0] = m;
    }
    __syncthreads();
    float var = red[0] * (1.0f / CC);
    out[(size_t)row * CC + tid] = dlt * rsqrtf(var + 1e-5f) * gg[tid] + bb[tid];
}

__device__ __forceinline__ float gelu_f(float x) {
    return 0.5f * x * (1.0f + erff(x * 0.70710678118654752f));
}

// ---------------- High-throughput tiled SGEMM ----------------
// C(M,N) = A(M,K) @ op(B) [+bias][gelu][+resid]; TRB: B is (N,K) else (K,N).
// Double-buffered smem, float4 global loads, 1 sync per K-step.
template<int BM, int BN, int BK, int TM, int TN, int TRB>
__global__ __launch_bounds__((BM / TM) * (BN / TN))
void gemm_k(const float* __restrict__ A, const float* __restrict__ B,
            float* __restrict__ C, int Kd, int Nc,
            const float* __restrict__ bias, int act,
            const float* __restrict__ resid,
            long long sA, long long sB, long long sC) {
    constexpr int NT  = (BM / TM) * (BN / TN);
    constexpr int KV  = BK / 4;                 // float4 per K-strip
    constexpr int ALD = BM * KV / NT;
    constexpr int BLD = BN * KV / NT;
    __shared__ __align__(16) float As[2][BK][BM + 4];
    __shared__ __align__(16) float Bs[2][BK][BN + 4];

    const int z = blockIdx.z;
    A += (long long)z * sA;
    B += (long long)z * sB;
    C += (long long)z * sC;
    const int i0 = blockIdx.y * BM, j0 = blockIdx.x * BN;
    const int tid = threadIdx.x;
    const int tx = tid % (BN / TN), ty = tid / (BN / TN);

    float4 ra[ALD], rb[BLD];
    float acc[TM][TN] = {};

    auto gload = [&](int k0) {
        #pragma unroll
        for (int q = 0; q < ALD; q++) {
            int f = tid + NT * q;
            int r = f / KV, kq = (f % KV) * 4;
            ra[q] = *reinterpret_cast<const float4*>(&A[(long long)(i0 + r) * Kd + k0 + kq]);
        }
        if (TRB) {
            #pragma unroll
            for (int q = 0; q < BLD; q++) {
                int f = tid + NT * q;
                int r = f / KV, kq = (f % KV) * 4;
                rb[q] = *reinterpret_cast<const float4*>(&B[(long long)(j0 + r) * Kd + k0 + kq]);
            }
        } else {
            #pragma unroll
            for (int q = 0; q < BLD; q++) {
                int f = tid + NT * q;
                int kk = f / (BN / 4), jc = (f % (BN / 4)) * 4;
                rb[q] = *reinterpret_cast<const float4*>(&B[(long long)(k0 + kk) * Nc + j0 + jc]);
            }
        }
    };
    auto sstore = [&](int bf) {
        #pragma unroll
        for (int q = 0; q < ALD; q++) {
            int f = tid + NT * q;
            int r = f / KV, kq = (f % KV) * 4;
            As[bf][kq + 0][r] = ra[q].x;
            As[bf][kq + 1][r] = ra[q].y;
            As[bf][kq + 2][r] = ra[q].z;
            As[bf][kq + 3][r] = ra[q].w;
        }
        if (TRB) {
            #pragma unroll
            for (int q = 0; q < BLD; q++) {
                int f = tid + NT * q;
                int r = f / KV, kq = (f % KV) * 4;
                Bs[bf][kq + 0][r] = rb[q].x;
                Bs[bf][kq + 1][r] = rb[q].y;
                Bs[bf][kq + 2][r] = rb[q].z;
                Bs[bf][kq + 3][r] = rb[q].w;
            }
        } else {
            #pragma unroll
            for (int q = 0; q < BLD; q++) {
                int f = tid + NT * q;
                int kk = f / (BN / 4), jc = (f % (BN / 4)) * 4;
                *reinterpret_cast<float4*>(&Bs[bf][kk][jc]) = rb[q];
            }
        }
    };
    auto comp = [&](int bf) {
        #pragma unroll
        for (int kk = 0; kk < BK; kk++) {
            float a[TM], b[TN];
            #pragma unroll
            for (int u = 0; u < TM; u++) a[u] = As[bf][kk][ty * TM + u];
            #pragma unroll
            for (int w = 0; w < TN; w++) b[w] = Bs[bf][kk][tx * TN + w];
            #pragma unroll
            for (int u = 0; u < TM; u++)
                #pragma unroll
                for (int w = 0; w < TN; w++)
                    acc[u][w] = fmaf(a[u], b[w], acc[u][w]);
        }
    };

    gload(0);
    sstore(0);
    __syncthreads();
    int nt = Kd / BK, bf = 0;
    for (int t = 0; t < nt; t++) {
        if (t + 1 < nt) gload((t + 1) * BK);
        comp(bf);
        if (t + 1 < nt) {
            sstore(bf ^ 1);
            __syncthreads();
            bf ^= 1;
        }
    }
    #pragma unroll
    for (int u = 0; u < TM; u++) {
        int row = i0 + ty * TM + u;
        #pragma unroll
        for (int w = 0; w < TN; w++) {
            int col = j0 + tx * TN + w;
            float v = acc[u][w];
            if (bias) v += bias[col];
            if (act == 1) v = gelu_f(v);
            long long idx = (long long)row * Nc + col;
            if (resid) v += resid[idx];
            C[idx] = v;
        }
    }
}

// ---------------- qkv split + q prescale ----------------
__global__ void split_kernel() {
    int gid = blockIdx.x * blockDim.x + threadIdx.x;
    if (gid >= NBH * MTOK * DH) return;
    int d = gid & 63;
    int m = (gid >> 6) & (MTOK - 1);
    int z = gid >> 16;
    int b = z >> 3, h = z & 7;
    const float* base = g_qkv + ((size_t)(b * MTOK + m)) * (3 * CC) + h * DH + d;
    g_q[gid] = base[0] * 0.125f;
    g_k[gid] = base[CC];
    g_v[gid] = base[2 * CC];
}

// ---------------- softmax + fused attn@xyz ----------------
__global__ void softmax_kernel() {
    int blk = blockIdx.x;                 // z*1024 + i
    int z = blk >> 10, i = blk & (MTOK - 1);
    int b = z >> 3;
    (void)i;
    float* p = g_attn + (size_t)blk * MTOK;
    int tid = threadIdx.x;                // 256
    float v0 = p[tid], v1 = p[tid + 256], v2 = p[tid + 512], v3 = p[tid + 768];
    float mx = fmaxf(fmaxf(v0, v1), fmaxf(v2, v3));
    __shared__ float red[8];
    #pragma unroll
    for (int o = 16; o; o >>= 1) mx = fmaxf(mx, __shfl_xor_sync(0xffffffffu, mx, o));
    if ((tid & 31) == 0) red[tid >> 5] = mx;
    __syncthreads();
    if (tid == 0) {
        float m = red[0];
        #pragma unroll
        for (int q = 1; q < 8; q++) m = fmaxf(m, red[q]);
        red[0] = m;
    }
    __syncthreads();
    mx = red[0];
    __syncthreads();
    float e0 = expf(v0 - mx), e1 = expf(v1 - mx), e2 = expf(v2 - mx), e3 = expf(v3 - mx);
    float s = ((e0 + e1) + e2) + e3;
    #pragma unroll
    for (int o = 16; o; o >>= 1) s += __shfl_xor_sync(0xffffffffu, s, o);
    if ((tid & 31) == 0) red[tid >> 5] = s;
    __syncthreads();
    if (tid == 0) {
        float m = 0.f;
        #pragma unroll
        for (int q = 0; q < 8; q++) m += red[q];
        red[0] = m;
    }
    __syncthreads();
    float inv = 1.0f / red[0];
    float p0 = e0 * inv, p1 = e1 * inv, p2 = e2 * inv, p3 = e3 * inv;
    p[tid] = p0; p[tid + 256] = p1; p[tid + 512] = p2; p[tid + 768] = p3;

    // fused attn @ xyz
    const float* xyzb = g_anchor + (size_t)b * MTOK * 3;
    float s0 = p0 * xyzb[tid * 3 + 0] + p1 * xyzb[(tid + 256) * 3 + 0]
             + p2 * xyzb[(tid + 512) * 3 + 0] + p3 * xyzb[(tid + 768) * 3 + 0];
    float s1 = p0 * xyzb[tid * 3 + 1] + p1 * xyzb[(tid + 256) * 3 + 1]
             + p2 * xyzb[(tid + 512) * 3 + 1] + p3 * xyzb[(tid + 768) * 3 + 1];
    float s2 = p0 * xyzb[tid * 3 + 2] + p1 * xyzb[(tid + 256) * 3 + 2]
             + p2 * xyzb[(tid + 512) * 3 + 2] + p3 * xyzb[(tid + 768) * 3 + 2];
    __shared__ float sr0[8], sr1[8], sr2[8];
    #pragma unroll
    for (int o = 16; o; o >>= 1) {
        s0 += __shfl_xor_sync(0xffffffffu, s0, o);
        s1 += __shfl_xor_sync(0xffffffffu, s1, o);
        s2 += __shfl_xor_sync(0xffffffffu, s2, o);
    }
    if ((tid & 31) == 0) { sr0[tid >> 5] = s0; sr1[tid >> 5] = s1; sr2[tid >> 5] = s2; }
    __syncthreads();
    if (tid == 0) {
        float a0 = 0, a1 = 0, a2 = 0;
        #pragma unroll
        for (int q = 0; q < 8; q++) { a0 += sr0[q]; a1 += sr1[q]; a2 += sr2[q]; }
        g_axyz[(size_t)blk * 3 + 0] = a0;
        g_axyz[(size_t)blk * 3 + 1] = a1;
        g_axyz[(size_t)blk * 3 + 2] = a2;
    }
}

// ---------------- combine out_v + spatial displacement projection ----------------
__global__ void combine_kernel(const float* __restrict__ Wsp) {
    int gid = blockIdx.x * blockDim.x + threadIdx.x;
    if (gid >= BB * MTOK * CC) return;
    int d = gid & 63;
    int h = (gid >> 6) & 7;
    int i = (gid >> 9) & (MTOK - 1);
    int b = gid >> 19;
    int z = b * 8 + h;
    float v = g_ov[((size_t)z * MTOK + i) * DH + d];
    const float* ax = g_axyz + ((size_t)z * MTOK + i) * 3;
    const float* xy = g_anchor + ((size_t)b * MTOK + i) * 3;
    float w0 = Wsp[d * 3 + 0], w1 = Wsp[d * 3 + 1], w2 = Wsp[d * 3 + 2];
    v += (ax[0] - xy[0]) * w0 + (ax[1] - xy[1]) * w1 + (ax[2] - xy[2]) * w2;
    g_attnout[((size_t)b * MTOK + i) * CC + h * DH + d] = v;
}

// ---------------- launch ----------------
extern "C" void kernel_launch(void* const* d_in, const int* in_sizes, int n_in,
                              void* d_out, int out_size) {
    const float* xyzs  = (const float*)d_in[0];
    const float* Wd    = (const float*)d_in[1];
    const float* Wqkv  = (const float*)d_in[2];
    const float* Wsp   = (const float*)d_in[3];
    const float* Wout  = (const float*)d_in[4];
    const float* bout  = (const float*)d_in[5];
    const float* ln1g  = (const float*)d_in[6];
    const float* ln1b  = (const float*)d_in[7];
    const float* Wff1  = (const float*)d_in[8];
    const float* bff1  = (const float*)d_in[9];
    const float* Wff2  = (const float*)d_in[10];
    const float* bff2  = (const float*)d_in[11];
    const float* ln2g  = (const float*)d_in[12];
    const float* ln2b  = (const float*)d_in[13];
    float* outp = (float*)d_out;

    float *p_feats, *p_xln, *p_qkv, *p_q, *p_k, *p_v, *p_ov, *p_attn, *p_ao, *p_hid;
    cudaGetSymbolAddress((void**)&p_feats, g_feats);
    cudaGetSymbolAddress((void**)&p_xln, g_xln);
    cudaGetSymbolAddress((void**)&p_qkv, g_qkv);
    cudaGetSymbolAddress((void**)&p_q, g_q);
    cudaGetSymbolAddress((void**)&p_k, g_k);
    cudaGetSymbolAddress((void**)&p_v, g_v);
    cudaGetSymbolAddress((void**)&p_ov, g_ov);
    cudaGetSymbolAddress((void**)&p_attn, g_attn);
    cudaGetSymbolAddress((void**)&p_ao, g_attnout);
    cudaGetSymbolAddress((void**)&p_hid, g_hid);

    fps_kernel<<<BB * TT, 1024>>>(xyzs);
    ballq_kernel<<<(BB * TT * 3 * MM + 255) / 256, 256>>>(xyzs);
    conv_kernel<<<BB * TT * MM, CC>>>(xyzs, Wd);

    for (int dep = 0; dep < 2; dep++) {
        const float* Wqkv_d = Wqkv + (size_t)dep * 3 * CC * CC;
        const float* Wsp_d  = Wsp  + (size_t)dep * DH * 3;
        const float* Wout_d = Wout + (size_t)dep * CC * CC;
        const float* bout_d = bout + (size_t)dep * CC;
        const float* l1g = ln1g + dep * CC, *l1b = ln1b + dep * CC;
        const float* Wff1_d = Wff1 + (size_t)dep * MLPD * CC;
        const float* bff1_d = bff1 + (size_t)dep * MLPD;
        const float* Wff2_d = Wff2 + (size_t)dep * CC * MLPD;
        const float* bff2_d = bff2 + (size_t)dep * CC;
        const float* l2g = ln2g + dep * CC, *l2b = ln2b + dep * CC;

        // LN1 + QKV  (M=2048, N=1536, K=512)
        ln_kernel<<<BB * MTOK, CC>>>(p_feats, p_xln, l1g, l1b);
        gemm_k<128, 128, 16, 8, 8, 1><<<dim3(1536 / 128, 2048 / 128, 1), 256>>>(
            p_xln, Wqkv_d, p_qkv, CC, 3 * CC, nullptr, 0, nullptr, 0, 0, 0);
        split_kernel<<<(NBH * MTOK * DH + 255) / 256, 256>>>();

        // dots = Q @ K^T  (16 x [1024,1024,64])
        gemm_k<128, 128, 16, 8, 8, 1><<<dim3(8, 8, NBH), 256>>>(
            p_q, p_k, p_attn, DH, MTOK, nullptr, 0, nullptr,
            (long long)MTOK * DH, (long long)MTOK * DH, (long long)MTOK * MTOK);
        softmax_kernel<<<NBH * MTOK, 256>>>();

        // out_v = attn @ V  (16 x [1024,64,1024])
        gemm_k<128, 64, 16, 8, 4, 0><<<dim3(1, 8, NBH), 256>>>(
            p_attn, p_v, p_ov, MTOK, DH, nullptr, 0, nullptr,
            (long long)MTOK * MTOK, (long long)MTOK * DH, (long long)MTOK * DH);

        combine_kernel<<<(BB * MTOK * CC + 255) / 256, 256>>>(Wsp_d);

        // out projection + bias + gelu + residual  (M=2048, N=512, K=512)
        gemm_k<128, 64, 16, 8, 4, 1><<<dim3(512 / 64, 2048 / 128, 1), 256>>>(
            p_ao, Wout_d, p_feats, CC, CC, bout_d, 1, p_feats, 0, 0, 0);

        // FF
        ln_kernel<<<BB * MTOK, CC>>>(p_feats, p_xln, l2g, l2b);
        gemm_k<128, 128, 16, 8, 8, 1><<<dim3(MLPD / 128, 2048 / 128, 1), 256>>>(
            p_xln, Wff1_d, p_hid, CC, MLPD, bff1_d, 1, nullptr, 0, 0, 0);
        float* cdst = (dep == 1) ? outp : p_feats;
        gemm_k<128, 64, 16, 8, 4, 1><<<dim3(512 / 64, 2048 / 128, 1), 256>>>(
            p_hid, Wff2_d, cdst, MLPD, CC, bff2_d, 0, p_feats, 0, 0, 0);
    }
}

// round 6
// speedup vs baseline: 1.0030x; 1.0030x over previous
#include <cuda_runtime.h>
#include <cuda_bf16.h>
#include <math.h>

// ---------------- Problem constants ----------------
#define BB 2
#define TT 4
#define NN 1024
#define MM 256
#define KK 32
#define CC 512
#define HH 8
#define DH 64
#define MTOK 1024
#define MLPD 2048
#define NBH 16

// ---------------- Scratch ----------------
__device__ float g_anchor[BB * TT * MM * 3];
__device__ int   g_bq[BB * TT * 3 * MM * KK];
__device__ float g_feats[BB * MTOK * CC];
__device__ float g_xln[BB * MTOK * CC];
__device__ float g_qkv[BB * MTOK * 3 * CC];
__device__ float g_q[NBH * MTOK * DH];
__device__ float g_k[NBH * MTOK * DH];
__device__ float g_v[NBH * MTOK * DH];
__device__ float g_ov[NBH * MTOK * DH];
__device__ float g_attn[(size_t)NBH * MTOK * MTOK];
__device__ float g_axyz[NBH * MTOK * 3];
__device__ float g_attnout[BB * MTOK * CC];
__device__ float g_hid[BB * MTOK * MLPD];

// ---------------- FPS ----------------
__global__ void fps_kernel(const float* __restrict__ xyzs) {
    int b = blockIdx.x >> 2, t = blockIdx.x & 3;
    const float* fr = xyzs + (size_t)(b * TT + t) * NN * 3;
    int tid = threadIdx.x, lane = tid & 31, wrp = tid >> 5;
    __shared__ float wv[32];
    __shared__ int wi[32];
    __shared__ int s_last;
    float px = fr[tid * 3 + 0], py = fr[tid * 3 + 1], pz = fr[tid * 3 + 2];
    float dist = 1e10f;
    int aoff = (b * TT + t) * MM;
    if (tid == 0) {
        g_anchor[(size_t)aoff * 3 + 0] = fr[0];
        g_anchor[(size_t)aoff * 3 + 1] = fr[1];
        g_anchor[(size_t)aoff * 3 + 2] = fr[2];
        s_last = 0;
    }
    __syncthreads();
    for (int it = 1; it < MM; ++it) {
        int last = s_last;
        float lx = fr[last * 3 + 0], ly = fr[last * 3 + 1], lz = fr[last * 3 + 2];
        float dx = px - lx, dy = py - ly, dz = pz - lz;
        float d = __fadd_rn(__fadd_rn(__fmul_rn(dx, dx), __fmul_rn(dy, dy)),
                            __fmul_rn(dz, dz));
        dist = fminf(dist, d);
        float bv = dist; int bi = tid;
        #pragma unroll
        for (int o = 16; o; o >>= 1) {
            float ov = __shfl_xor_sync(0xffffffffu, bv, o);
            int   oi = __shfl_xor_sync(0xffffffffu, bi, o);
            if (ov > bv || (ov == bv && oi < bi)) { bv = ov; bi = oi; }
        }
        if (lane == 0) { wv[wrp] = bv; wi[wrp] = bi; }
        __syncthreads();
        if (tid < 32) {
            bv = wv[tid]; bi = wi[tid];
            #pragma unroll
            for (int o = 16; o; o >>= 1) {
                float ov = __shfl_xor_sync(0xffffffffu, bv, o);
                int   oi = __shfl_xor_sync(0xffffffffu, bi, o);
                if (ov > bv || (ov == bv && oi < bi)) { bv = ov; bi = oi; }
            }
            if (tid == 0) {
                s_last = bi;
                g_anchor[((size_t)(aoff + it)) * 3 + 0] = fr[bi * 3 + 0];
                g_anchor[((size_t)(aoff + it)) * 3 + 1] = fr[bi * 3 + 1];
                g_anchor[((size_t)(aoff + it)) * 3 + 2] = fr[bi * 3 + 2];
            }
        }
        __syncthreads();
    }
}

// ---------------- Ball query ----------------
__global__ void ballq_kernel(const float* __restrict__ xyzs) {
    int gid = blockIdx.x * blockDim.x + threadIdx.x;
    if (gid >= BB * TT * 3 * MM) return;
    int mm = gid & (MM - 1);
    int r = gid >> 8;
    int tap = r % 3; r /= 3;
    int t = r & 3;
    int b = r >> 2;
    int src = t - 1 + tap;
    src = src < 0 ? 0 : (src > 3 ? 3 : src);
    const float* nb = xyzs + (size_t)(b * TT + src) * NN * 3;
    const float* an = g_anchor + ((size_t)((b * TT + t) * MM + mm)) * 3;
    float ax = an[0], ay = an[1], az = an[2];
    int* o = g_bq + (size_t)gid * KK;
    int cnt = 0;
    for (int j = 0; j < NN && cnt < KK; ++j) {
        float dx = ax - nb[j * 3], dy = ay - nb[j * 3 + 1], dz = az - nb[j * 3 + 2];
        float d2 = __fadd_rn(__fadd_rn(__fmul_rn(dx, dx), __fmul_rn(dy, dy)),
                             __fmul_rn(dz, dz));
        if (d2 < 1.0f) o[cnt++] = j;
    }
    int fill = (cnt > 0) ? o[0] : 0;
    for (int c = cnt; c < KK; ++c) o[c] = fill;
}

// ---------------- p4dconv ----------------
__global__ void conv_kernel(const float* __restrict__ xyzs, const float* __restrict__ Wd) {
    int blk = blockIdx.x;
    int mm = blk & (MM - 1);
    int t = (blk >> 8) & 3;
    int b = blk >> 10;
    int tid = threadIdx.x;
    __shared__ float sd[96][4];
    const float* an = g_anchor + (size_t)blk * 3;
    if (tid < 96) {
        int tap = tid >> 5, k = tid & 31;
        int src = t - 1 + tap;
        src = src < 0 ? 0 : (src > 3 ? 3 : src);
        const float* nb = xyzs + (size_t)(b * TT + src) * NN * 3;
        int j = g_bq[(((size_t)(b * TT + t) * 3 + tap) * MM + mm) * KK + k];
        sd[tid][0] = nb[j * 3 + 0] - an[0];
        sd[tid][1] = nb[j * 3 + 1] - an[1];
        sd[tid][2] = nb[j * 3 + 2] - an[2];
        sd[tid][3] = (float)(tap - 1);
    }
    __syncthreads();
    float w0 = Wd[tid * 4 + 0], w1 = Wd[tid * 4 + 1],
          w2 = Wd[tid * 4 + 2], w3 = Wd[tid * 4 + 3];
    float best = -1e30f;
    #pragma unroll 4
    for (int r = 0; r < 96; ++r) {
        float v = sd[r][0] * w0 + sd[r][1] * w1 + sd[r][2] * w2 + sd[r][3] * w3;
        best = fmaxf(best, v);
    }
    g_feats[(size_t)blk * CC + tid] = fmaxf(best, 0.0f);
}

// ---------------- LayerNorm ----------------
__global__ void ln_kernel(const float* __restrict__ in, float* __restrict__ out,
                          const float* __restrict__ gg, const float* __restrict__ bb) {
    int row = blockIdx.x, tid = threadIdx.x;
    float x = in[(size_t)row * CC + tid];
    __shared__ float red[16];
    float s = x;
    #pragma unroll
    for (int o = 16; o; o >>= 1) s += __shfl_xor_sync(0xffffffffu, s, o);
    if ((tid & 31) == 0) red[tid >> 5] = s;
    __syncthreads();
    if (tid == 0) {
        float m = 0.f;
        #pragma unroll
        for (int i = 0; i < 16; i++) m += red[i];
        red[0] = m;
    }
    __syncthreads();
    float mu = red[0] * (1.0f / CC);
    float dlt = x - mu;
    __syncthreads();
    float s2 = dlt * dlt;
    #pragma unroll
    for (int o = 16; o; o >>= 1) s2 += __shfl_xor_sync(0xffffffffu, s2, o);
    if ((tid & 31) == 0) red[tid >> 5] = s2;
    __syncthreads();
    if (tid == 0) {
        float m = 0.f;
        #pragma unroll
        for (int i = 0; i < 16; i++) m += red[i];
        red[0] = m;
    }
    __syncthreads();
    float var = red[0] * (1.0f / CC);
    out[(size_t)row * CC + tid] = dlt * rsqrtf(var + 1e-5f) * gg[tid] + bb[tid];
}

__device__ __forceinline__ float gelu_f(float x) {
    return 0.5f * x * (1.0f + erff(x * 0.70710678118654752f));
}

// ---------------- High-throughput tiled SGEMM ----------------
// C(M,N) = A(M,K) @ op(B) [+bias][gelu][+resid]; TRB: B is (N,K) else (K,N).
// Double-buffered smem, float4 global loads, 1 sync per K-step.
template<int BM, int BN, int BK, int TM, int TN, int TRB>
__global__ __launch_bounds__((BM / TM) * (BN / TN))
void gemm_k(const float* __restrict__ A, const float* __restrict__ B,
            float* __restrict__ C, int Kd, int Nc,
            const float* __restrict__ bias, int act,
            const float* __restrict__ resid,
            long long sA, long long sB, long long sC) {
    constexpr int NT  = (BM / TM) * (BN / TN);
    constexpr int KV  = BK / 4;                 // float4 per K-strip
    constexpr int ALD = BM * KV / NT;
    constexpr int BLD = BN * KV / NT;
    __shared__ __align__(16) float As[2][BK][BM + 4];
    __shared__ __align__(16) float Bs[2][BK][BN + 4];

    const int z = blockIdx.z;
    A += (long long)z * sA;
    B += (long long)z * sB;
    C += (long long)z * sC;
    const int i0 = blockIdx.y * BM, j0 = blockIdx.x * BN;
    const int tid = threadIdx.x;
    const int tx = tid % (BN / TN), ty = tid / (BN / TN);

    float4 ra[ALD], rb[BLD];
    float acc[TM][TN] = {};

    auto gload = [&](int k0) {
        #pragma unroll
        for (int q = 0; q < ALD; q++) {
            int f = tid + NT * q;
            int r = f / KV, kq = (f % KV) * 4;
            ra[q] = *reinterpret_cast<const float4*>(&A[(long long)(i0 + r) * Kd + k0 + kq]);
        }
        if (TRB) {
            #pragma unroll
            for (int q = 0; q < BLD; q++) {
                int f = tid + NT * q;
                int r = f / KV, kq = (f % KV) * 4;
                rb[q] = *reinterpret_cast<const float4*>(&B[(long long)(j0 + r) * Kd + k0 + kq]);
            }
        } else {
            #pragma unroll
            for (int q = 0; q < BLD; q++) {
                int f = tid + NT * q;
                int kk = f / (BN / 4), jc = (f % (BN / 4)) * 4;
                rb[q] = *reinterpret_cast<const float4*>(&B[(long long)(k0 + kk) * Nc + j0 + jc]);
            }
        }
    };
    auto sstore = [&](int bf) {
        #pragma unroll
        for (int q = 0; q < ALD; q++) {
            int f = tid + NT * q;
            int r = f / KV, kq = (f % KV) * 4;
            As[bf][kq + 0][r] = ra[q].x;
            As[bf][kq + 1][r] = ra[q].y;
            As[bf][kq + 2][r] = ra[q].z;
            As[bf][kq + 3][r] = ra[q].w;
        }
        if (TRB) {
            #pragma unroll
            for (int q = 0; q < BLD; q++) {
                int f = tid + NT * q;
                int r = f / KV, kq = (f % KV) * 4;
                Bs[bf][kq + 0][r] = rb[q].x;
                Bs[bf][kq + 1][r] = rb[q].y;
                Bs[bf][kq + 2][r] = rb[q].z;
                Bs[bf][kq + 3][r] = rb[q].w;
            }
        } else {
            #pragma unroll
            for (int q = 0; q < BLD; q++) {
                int f = tid + NT * q;
                int kk = f / (BN / 4), jc = (f % (BN / 4)) * 4;
                *reinterpret_cast<float4*>(&Bs[bf][kk][jc]) = rb[q];
            }
        }
    };
    auto comp = [&](int bf) {
        #pragma unroll
        for (int kk = 0; kk < BK; kk++) {
            float a[TM], b[TN];
            #pragma unroll
            for (int u = 0; u < TM; u++) a[u] = As[bf][kk][ty * TM + u];
            #pragma unroll
            for (int w = 0; w < TN; w++) b[w] = Bs[bf][kk][tx * TN + w];
            #pragma unroll
            for (int u = 0; u < TM; u++)
                #pragma unroll
                for (int w = 0; w < TN; w++)
                    acc[u][w] = fmaf(a[u], b[w], acc[u][w]);
        }
    };

    gload(0);
    sstore(0);
    __syncthreads();
    int nt = Kd / BK, bf = 0;
    for (int t = 0; t < nt; t++) {
        if (t + 1 < nt) gload((t + 1) * BK);
        comp(bf);
        if (t + 1 < nt) {
            sstore(bf ^ 1);
            __syncthreads();
            bf ^= 1;
        }
    }
    #pragma unroll
    for (int u = 0; u < TM; u++) {
        int row = i0 + ty * TM + u;
        #pragma unroll
        for (int w = 0; w < TN; w++) {
            int col = j0 + tx * TN + w;
            float v = acc[u][w];
            if (bias) v += bias[col];
            if (act == 1) v = gelu_f(v);
            long long idx = (long long)row * Nc + col;
            if (resid) v += resid[idx];
            C[idx] = v;
        }
    }
}

// ---------------- qkv split + q prescale ----------------
__global__ void split_kernel() {
    int gid = blockIdx.x * blockDim.x + threadIdx.x;
    if (gid >= NBH * MTOK * DH) return;
    int d = gid & 63;
    int m = (gid >> 6) & (MTOK - 1);
    int z = gid >> 16;
    int b = z >> 3, h = z & 7;
    const float* base = g_qkv + ((size_t)(b * MTOK + m)) * (3 * CC) + h * DH + d;
    g_q[gid] = base[0] * 0.125f;
    g_k[gid] = base[CC];
    g_v[gid] = base[2 * CC];
}

// ---------------- softmax + fused attn@xyz ----------------
__global__ void softmax_kernel() {
    int blk = blockIdx.x;                 // z*1024 + i
    int z = blk >> 10, i = blk & (MTOK - 1);
    int b = z >> 3;
    (void)i;
    float* p = g_attn + (size_t)blk * MTOK;
    int tid = threadIdx.x;                // 256
    float v0 = p[tid], v1 = p[tid + 256], v2 = p[tid + 512], v3 = p[tid + 768];
    float mx = fmaxf(fmaxf(v0, v1), fmaxf(v2, v3));
    __shared__ float red[8];
    #pragma unroll
    for (int o = 16; o; o >>= 1) mx = fmaxf(mx, __shfl_xor_sync(0xffffffffu, mx, o));
    if ((tid & 31) == 0) red[tid >> 5] = mx;
    __syncthreads();
    if (tid == 0) {
        float m = red[0];
        #pragma unroll
        for (int q = 1; q < 8; q++) m = fmaxf(m, red[q]);
        red[0] = m;
    }
    __syncthreads();
    mx = red[0];
    __syncthreads();
    float e0 = expf(v0 - mx), e1 = expf(v1 - mx), e2 = expf(v2 - mx), e3 = expf(v3 - mx);
    float s = ((e0 + e1) + e2) + e3;
    #pragma unroll
    for (int o = 16; o; o >>= 1) s += __shfl_xor_sync(0xffffffffu, s, o);
    if ((tid & 31) == 0) red[tid >> 5] = s;
    __syncthreads();
    if (tid == 0) {
        float m = 0.f;
        #pragma unroll
        for (int q = 0; q < 8; q++) m += red[q];
        red[0] = m;
    }
    __syncthreads();
    float inv = 1.0f / red[0];
    float p0 = e0 * inv, p1 = e1 * inv, p2 = e2 * inv, p3 = e3 * inv;
    p[tid] = p0; p[tid + 256] = p1; p[tid + 512] = p2; p[tid + 768] = p3;

    // fused attn @ xyz
    const float* xyzb = g_anchor + (size_t)b * MTOK * 3;
    float s0 = p0 * xyzb[tid * 3 + 0] + p1 * xyzb[(tid + 256) * 3 + 0]
             + p2 * xyzb[(tid + 512) * 3 + 0] + p3 * xyzb[(tid + 768) * 3 + 0];
    float s1 = p0 * xyzb[tid * 3 + 1] + p1 * xyzb[(tid + 256) * 3 + 1]
             + p2 * xyzb[(tid + 512) * 3 + 1] + p3 * xyzb[(tid + 768) * 3 + 1];
    float s2 = p0 * xyzb[tid * 3 + 2] + p1 * xyzb[(tid + 256) * 3 + 2]
             + p2 * xyzb[(tid + 512) * 3 + 2] + p3 * xyzb[(tid + 768) * 3 + 2];
    __shared__ float sr0[8], sr1[8], sr2[8];
    #pragma unroll
    for (int o = 16; o; o >>= 1) {
        s0 += __shfl_xor_sync(0xffffffffu, s0, o);
        s1 += __shfl_xor_sync(0xffffffffu, s1, o);
        s2 += __shfl_xor_sync(0xffffffffu, s2, o);
    }
    if ((tid & 31) == 0) { sr0[tid >> 5] = s0; sr1[tid >> 5] = s1; sr2[tid >> 5] = s2; }
    __syncthreads();
    if (tid == 0) {
        float a0 = 0, a1 = 0, a2 = 0;
        #pragma unroll
        for (int q = 0; q < 8; q++) { a0 += sr0[q]; a1 += sr1[q]; a2 += sr2[q]; }
        g_axyz[(size_t)blk * 3 + 0] = a0;
        g_axyz[(size_t)blk * 3 + 1] = a1;
        g_axyz[(size_t)blk * 3 + 2] = a2;
    }
}

// ---------------- combine out_v + spatial displacement projection ----------------
__global__ void combine_kernel(const float* __restrict__ Wsp) {
    int gid = blockIdx.x * blockDim.x + threadIdx.x;
    if (gid >= BB * MTOK * CC) return;
    int d = gid & 63;
    int h = (gid >> 6) & 7;
    int i = (gid >> 9) & (MTOK - 1);
    int b = gid >> 19;
    int z = b * 8 + h;
    float v = g_ov[((size_t)z * MTOK + i) * DH + d];
    const float* ax = g_axyz + ((size_t)z * MTOK + i) * 3;
    const float* xy = g_anchor + ((size_t)b * MTOK + i) * 3;
    float w0 = Wsp[d * 3 + 0], w1 = Wsp[d * 3 + 1], w2 = Wsp[d * 3 + 2];
    v += (ax[0] - xy[0]) * w0 + (ax[1] - xy[1]) * w1 + (ax[2] - xy[2]) * w2;
    g_attnout[((size_t)b * MTOK + i) * CC + h * DH + d] = v;
}

// ---------------- launch ----------------
extern "C" void kernel_launch(void* const* d_in, const int* in_sizes, int n_in,
                              void* d_out, int out_size) {
    const float* xyzs  = (const float*)d_in[0];
    const float* Wd    = (const float*)d_in[1];
    const float* Wqkv  = (const float*)d_in[2];
    const float* Wsp   = (const float*)d_in[3];
    const float* Wout  = (const float*)d_in[4];
    const float* bout  = (const float*)d_in[5];
    const float* ln1g  = (const float*)d_in[6];
    const float* ln1b  = (const float*)d_in[7];
    const float* Wff1  = (const float*)d_in[8];
    const float* bff1  = (const float*)d_in[9];
    const float* Wff2  = (const float*)d_in[10];
    const float* bff2  = (const float*)d_in[11];
    const float* ln2g  = (const float*)d_in[12];
    const float* ln2b  = (const float*)d_in[13];
    float* outp = (float*)d_out;

    float *p_feats, *p_xln, *p_qkv, *p_q, *p_k, *p_v, *p_ov, *p_attn, *p_ao, *p_hid;
    cudaGetSymbolAddress((void**)&p_feats, g_feats);
    cudaGetSymbolAddress((void**)&p_xln, g_xln);
    cudaGetSymbolAddress((void**)&p_qkv, g_qkv);
    cudaGetSymbolAddress((void**)&p_q, g_q);
    cudaGetSymbolAddress((void**)&p_k, g_k);
    cudaGetSymbolAddress((void**)&p_v, g_v);
    cudaGetSymbolAddress((void**)&p_ov, g_ov);
    cudaGetSymbolAddress((void**)&p_attn, g_attn);
    cudaGetSymbolAddress((void**)&p_ao, g_attnout);
    cudaGetSymbolAddress((void**)&p_hid, g_hid);

    fps_kernel<<<BB * TT, 1024>>>(xyzs);
    ballq_kernel<<<(BB * TT * 3 * MM + 255) / 256, 256>>>(xyzs);
    conv_kernel<<<BB * TT * MM, CC>>>(xyzs, Wd);

    for (int dep = 0; dep < 2; dep++) {
        const float* Wqkv_d = Wqkv + (size_t)dep * 3 * CC * CC;
        const float* Wsp_d  = Wsp  + (size_t)dep * DH * 3;
        const float* Wout_d = Wout + (size_t)dep * CC * CC;
        const float* bout_d = bout + (size_t)dep * CC;
        const float* l1g = ln1g + dep * CC, *l1b = ln1b + dep * CC;
        const float* Wff1_d = Wff1 + (size_t)dep * MLPD * CC;
        const float* bff1_d = bff1 + (size_t)dep * MLPD;
        const float* Wff2_d = Wff2 + (size_t)dep * CC * MLPD;
        const float* bff2_d = bff2 + (size_t)dep * CC;
        const float* l2g = ln2g + dep * CC, *l2b = ln2b + dep * CC;

        // LN1 + QKV  (M=2048, N=1536, K=512)
        ln_kernel<<<BB * MTOK, CC>>>(p_feats, p_xln, l1g, l1b);
        gemm_k<128, 128, 16, 8, 8, 1><<<dim3(1536 / 128, 2048 / 128, 1), 256>>>(
            p_xln, Wqkv_d, p_qkv, CC, 3 * CC, nullptr, 0, nullptr, 0, 0, 0);
        split_kernel<<<(NBH * MTOK * DH + 255) / 256, 256>>>();

        // dots = Q @ K^T  (16 x [1024,1024,64])
        gemm_k<128, 128, 16, 8, 8, 1><<<dim3(8, 8, NBH), 256>>>(
            p_q, p_k, p_attn, DH, MTOK, nullptr, 0, nullptr,
            (long long)MTOK * DH, (long long)MTOK * DH, (long long)MTOK * MTOK);
        softmax_kernel<<<NBH * MTOK, 256>>>();

        // out_v = attn @ V  (16 x [1024,64,1024])
        gemm_k<128, 64, 16, 8, 4, 0><<<dim3(1, 8, NBH), 256>>>(
            p_attn, p_v, p_ov, MTOK, DH, nullptr, 0, nullptr,
            (long long)MTOK * MTOK, (long long)MTOK * DH, (long long)MTOK * DH);

        combine_kernel<<<(BB * MTOK * CC + 255) / 256, 256>>>(Wsp_d);

        // out projection + bias + gelu + residual  (M=2048, N=512, K=512)
        gemm_k<128, 64, 16, 8, 4, 1><<<dim3(512 / 64, 2048 / 128, 1), 256>>>(
            p_ao, Wout_d, p_feats, CC, CC, bout_d, 1, p_feats, 0, 0, 0);

        // FF
        ln_kernel<<<BB * MTOK, CC>>>(p_feats, p_xln, l2g, l2b);
        gemm_k<128, 128, 16, 8, 8, 1><<<dim3(MLPD / 128, 2048 / 128, 1), 256>>>(
            p_xln, Wff1_d, p_hid, CC, MLPD, bff1_d, 1, nullptr, 0, 0, 0);
        float* cdst = (dep == 1) ? outp : p_feats;
        gemm_k<128, 64, 16, 8, 4, 1><<<dim3(512 / 64, 2048 / 128, 1), 256>>>(
            p_hid, Wff2_d, cdst, MLPD, CC, bff2_d, 0, p_feats, 0, 0, 0);
    }
}

// round 7
// speedup vs baseline: 1.0041x; 1.0011x over previous
#include <cuda_runtime.h>
#include <cuda_bf16.h>
#include <math.h>

// ---------------- Problem constants ----------------
#define BB 2
#define TT 4
#define NN 1024
#define MM 256
#define KK 32
#define CC 512
#define HH 8
#define DH 64
#define MTOK 1024
#define MLPD 2048
#define NBH 16

// ---------------- Scratch ----------------
__device__ float g_anchor[BB * TT * MM * 3];
__device__ int   g_bq[BB * TT * 3 * MM * KK];
__device__ float g_feats[BB * MTOK * CC];
__device__ float g_xln[BB * MTOK * CC];
__device__ float g_qkv[BB * MTOK * 3 * CC];
__device__ float g_q[NBH * MTOK * DH];
__device__ float g_k[NBH * MTOK * DH];
__device__ float g_v[NBH * MTOK * DH];
__device__ float g_ov[NBH * MTOK * DH];
__device__ float g_attn[(size_t)NBH * MTOK * MTOK];
__device__ float g_axyz[NBH * MTOK * 3];
__device__ float g_attnout[BB * MTOK * CC];
__device__ float g_hid[BB * MTOK * MLPD];

// ---------------- FPS ----------------
__global__ void fps_kernel(const float* __restrict__ xyzs) {
    int b = blockIdx.x >> 2, t = blockIdx.x & 3;
    const float* fr = xyzs + (size_t)(b * TT + t) * NN * 3;
    int tid = threadIdx.x, lane = tid & 31, wrp = tid >> 5;
    __shared__ float wv[32];
    __shared__ int wi[32];
    __shared__ int s_last;
    float px = fr[tid * 3 + 0], py = fr[tid * 3 + 1], pz = fr[tid * 3 + 2];
    float dist = 1e10f;
    int aoff = (b * TT + t) * MM;
    if (tid == 0) {
        g_anchor[(size_t)aoff * 3 + 0] = fr[0];
        g_anchor[(size_t)aoff * 3 + 1] = fr[1];
        g_anchor[(size_t)aoff * 3 + 2] = fr[2];
        s_last = 0;
    }
    __syncthreads();
    for (int it = 1; it < MM; ++it) {
        int last = s_last;
        float lx = fr[last * 3 + 0], ly = fr[last * 3 + 1], lz = fr[last * 3 + 2];
        float dx = px - lx, dy = py - ly, dz = pz - lz;
        float d = __fadd_rn(__fadd_rn(__fmul_rn(dx, dx), __fmul_rn(dy, dy)),
                            __fmul_rn(dz, dz));
        dist = fminf(dist, d);
        float bv = dist; int bi = tid;
        #pragma unroll
        for (int o = 16; o; o >>= 1) {
            float ov = __shfl_xor_sync(0xffffffffu, bv, o);
            int   oi = __shfl_xor_sync(0xffffffffu, bi, o);
            if (ov > bv || (ov == bv && oi < bi)) { bv = ov; bi = oi; }
        }
        if (lane == 0) { wv[wrp] = bv; wi[wrp] = bi; }
        __syncthreads();
        if (tid < 32) {
            bv = wv[tid]; bi = wi[tid];
            #pragma unroll
            for (int o = 16; o; o >>= 1) {
                float ov = __shfl_xor_sync(0xffffffffu, bv, o);
                int   oi = __shfl_xor_sync(0xffffffffu, bi, o);
                if (ov > bv || (ov == bv && oi < bi)) { bv = ov; bi = oi; }
            }
            if (tid == 0) {
                s_last = bi;
                g_anchor[((size_t)(aoff + it)) * 3 + 0] = fr[bi * 3 + 0];
                g_anchor[((size_t)(aoff + it)) * 3 + 1] = fr[bi * 3 + 1];
                g_anchor[((size_t)(aoff + it)) * 3 + 2] = fr[bi * 3 + 2];
            }
        }
        __syncthreads();
    }
}

// ---------------- Ball query ----------------
__global__ void ballq_kernel(const float* __restrict__ xyzs) {
    int gid = blockIdx.x * blockDim.x + threadIdx.x;
    if (gid >= BB * TT * 3 * MM) return;
    int mm = gid & (MM - 1);
    int r = gid >> 8;
    int tap = r % 3; r /= 3;
    int t = r & 3;
    int b = r >> 2;
    int src = t - 1 + tap;
    src = src < 0 ? 0 : (src > 3 ? 3 : src);
    const float* nb = xyzs + (size_t)(b * TT + src) * NN * 3;
    const float* an = g_anchor + ((size_t)((b * TT + t) * MM + mm)) * 3;
    float ax = an[0], ay = an[1], az = an[2];
    int* o = g_bq + (size_t)gid * KK;
    int cnt = 0;
    for (int j = 0; j < NN && cnt < KK; ++j) {
        float dx = ax - nb[j * 3], dy = ay - nb[j * 3 + 1], dz = az - nb[j * 3 + 2];
        float d2 = __fadd_rn(__fadd_rn(__fmul_rn(dx, dx), __fmul_rn(dy, dy)),
                             __fmul_rn(dz, dz));
        if (d2 < 1.0f) o[cnt++] = j;
    }
    int fill = (cnt > 0) ? o[0] : 0;
    for (int c = cnt; c < KK; ++c) o[c] = fill;
}

// ---------------- p4dconv ----------------
__global__ void conv_kernel(const float* __restrict__ xyzs, const float* __restrict__ Wd) {
    int blk = blockIdx.x;
    int mm = blk & (MM - 1);
    int t = (blk >> 8) & 3;
    int b = blk >> 10;
    int tid = threadIdx.x;
    __shared__ float sd[96][4];
    const float* an = g_anchor + (size_t)blk * 3;
    if (tid < 96) {
        int tap = tid >> 5, k = tid & 31;
        int src = t - 1 + tap;
        src = src < 0 ? 0 : (src > 3 ? 3 : src);
        const float* nb = xyzs + (size_t)(b * TT + src) * NN * 3;
        int j = g_bq[(((size_t)(b * TT + t) * 3 + tap) * MM + mm) * KK + k];
        sd[tid][0] = nb[j * 3 + 0] - an[0];
        sd[tid][1] = nb[j * 3 + 1] - an[1];
        sd[tid][2] = nb[j * 3 + 2] - an[2];
        sd[tid][3] = (float)(tap - 1);
    }
    __syncthreads();
    float w0 = Wd[tid * 4 + 0], w1 = Wd[tid * 4 + 1],
          w2 = Wd[tid * 4 + 2], w3 = Wd[tid * 4 + 3];
    float best = -1e30f;
    #pragma unroll 4
    for (int r = 0; r < 96; ++r) {
        float v = sd[r][0] * w0 + sd[r][1] * w1 + sd[r][2] * w2 + sd[r][3] * w3;
        best = fmaxf(best, v);
    }
    g_feats[(size_t)blk * CC + tid] = fmaxf(best, 0.0f);
}

// ---------------- LayerNorm ----------------
__global__ void ln_kernel(const float* __restrict__ in, float* __restrict__ out,
                          const float* __restrict__ gg, const float* __restrict__ bb) {
    int row = blockIdx.x, tid = threadIdx.x;
    float x = in[(size_t)row * CC + tid];
    __shared__ float red[16];
    float s = x;
    #pragma unroll
    for (int o = 16; o; o >>= 1) s += __shfl_xor_sync(0xffffffffu, s, o);
    if ((tid & 31) == 0) red[tid >> 5] = s;
    __syncthreads();
    if (tid == 0) {
        float m = 0.f;
        #pragma unroll
        for (int i = 0; i < 16; i++) m += red[i];
        red[0] = m;
    }
    __syncthreads();
    float mu = red[0] * (1.0f / CC);
    float dlt = x - mu;
    __syncthreads();
    float s2 = dlt * dlt;
    #pragma unroll
    for (int o = 16; o; o >>= 1) s2 += __shfl_xor_sync(0xffffffffu, s2, o);
    if ((tid & 31) == 0) red[tid >> 5] = s2;
    __syncthreads();
    if (tid == 0) {
        float m = 0.f;
        #pragma unroll
        for (int i = 0; i < 16; i++) m += red[i];
        red[0] = m;
    }
    __syncthreads();
    float var = red[0] * (1.0f / CC);
    out[(size_t)row * CC + tid] = dlt * rsqrtf(var + 1e-5f) * gg[tid] + bb[tid];
}

__device__ __forceinline__ float gelu_f(float x) {
    return 0.5f * x * (1.0f + erff(x * 0.70710678118654752f));
}

// ---------------- High-throughput tiled SGEMM ----------------
// C(M,N) = A(M,K) @ op(B) [+bias][gelu][+resid]; TRB: B is (N,K) else (K,N).
// Double-buffered smem, float4 global loads, 1 sync per K-step.
template<int BM, int BN, int BK, int TM, int TN, int TRB>
__global__ __launch_bounds__((BM / TM) * (BN / TN))
void gemm_k(const float* __restrict__ A, const float* __restrict__ B,
            float* __restrict__ C, int Kd, int Nc,
            const float* __restrict__ bias, int act,
            const float* __restrict__ resid,
            long long sA, long long sB, long long sC) {
    constexpr int NT  = (BM / TM) * (BN / TN);
    constexpr int KV  = BK / 4;                 // float4 per K-strip
    constexpr int ALD = BM * KV / NT;
    constexpr int BLD = BN * KV / NT;
    __shared__ __align__(16) float As[2][BK][BM + 4];
    __shared__ __align__(16) float Bs[2][BK][BN + 4];

    const int z = blockIdx.z;
    A += (long long)z * sA;
    B += (long long)z * sB;
    C += (long long)z * sC;
    const int i0 = blockIdx.y * BM, j0 = blockIdx.x * BN;
    const int tid = threadIdx.x;
    const int tx = tid % (BN / TN), ty = tid / (BN / TN);

    float4 ra[ALD], rb[BLD];
    float acc[TM][TN] = {};

    auto gload = [&](int k0) {
        #pragma unroll
        for (int q = 0; q < ALD; q++) {
            int f = tid + NT * q;
            int r = f / KV, kq = (f % KV) * 4;
            ra[q] = *reinterpret_cast<const float4*>(&A[(long long)(i0 + r) * Kd + k0 + kq]);
        }
        if (TRB) {
            #pragma unroll
            for (int q = 0; q < BLD; q++) {
                int f = tid + NT * q;
                int r = f / KV, kq = (f % KV) * 4;
                rb[q] = *reinterpret_cast<const float4*>(&B[(long long)(j0 + r) * Kd + k0 + kq]);
            }
        } else {
            #pragma unroll
            for (int q = 0; q < BLD; q++) {
                int f = tid + NT * q;
                int kk = f / (BN / 4), jc = (f % (BN / 4)) * 4;
                rb[q] = *reinterpret_cast<const float4*>(&B[(long long)(k0 + kk) * Nc + j0 + jc]);
            }
        }
    };
    auto sstore = [&](int bf) {
        #pragma unroll
        for (int q = 0; q < ALD; q++) {
            int f = tid + NT * q;
            int r = f / KV, kq = (f % KV) * 4;
            As[bf][kq + 0][r] = ra[q].x;
            As[bf][kq + 1][r] = ra[q].y;
            As[bf][kq + 2][r] = ra[q].z;
            As[bf][kq + 3][r] = ra[q].w;
        }
        if (TRB) {
            #pragma unroll
            for (int q = 0; q < BLD; q++) {
                int f = tid + NT * q;
                int r = f / KV, kq = (f % KV) * 4;
                Bs[bf][kq + 0][r] = rb[q].x;
                Bs[bf][kq + 1][r] = rb[q].y;
                Bs[bf][kq + 2][r] = rb[q].z;
                Bs[bf][kq + 3][r] = rb[q].w;
            }
        } else {
            #pragma unroll
            for (int q = 0; q < BLD; q++) {
                int f = tid + NT * q;
                int kk = f / (BN / 4), jc = (f % (BN / 4)) * 4;
                *reinterpret_cast<float4*>(&Bs[bf][kk][jc]) = rb[q];
            }
        }
    };
    auto comp = [&](int bf) {
        #pragma unroll
        for (int kk = 0; kk < BK; kk++) {
            float a[TM], b[TN];
            #pragma unroll
            for (int u = 0; u < TM; u++) a[u] = As[bf][kk][ty * TM + u];
            #pragma unroll
            for (int w = 0; w < TN; w++) b[w] = Bs[bf][kk][tx * TN + w];
            #pragma unroll
            for (int u = 0; u < TM; u++)
                #pragma unroll
                for (int w = 0; w < TN; w++)
                    acc[u][w] = fmaf(a[u], b[w], acc[u][w]);
        }
    };

    gload(0);
    sstore(0);
    __syncthreads();
    int nt = Kd / BK, bf = 0;
    for (int t = 0; t < nt; t++) {
        if (t + 1 < nt) gload((t + 1) * BK);
        comp(bf);
        if (t + 1 < nt) {
            sstore(bf ^ 1);
            __syncthreads();
            bf ^= 1;
        }
    }
    #pragma unroll
    for (int u = 0; u < TM; u++) {
        int row = i0 + ty * TM + u;
        #pragma unroll
        for (int w = 0; w < TN; w++) {
            int col = j0 + tx * TN + w;
            float v = acc[u][w];
            if (bias) v += bias[col];
            if (act == 1) v = gelu_f(v);
            long long idx = (long long)row * Nc + col;
            if (resid) v += resid[idx];
            C[idx] = v;
        }
    }
}

// ---------------- qkv split + q prescale ----------------
__global__ void split_kernel() {
    int gid = blockIdx.x * blockDim.x + threadIdx.x;
    if (gid >= NBH * MTOK * DH) return;
    int d = gid & 63;
    int m = (gid >> 6) & (MTOK - 1);
    int z = gid >> 16;
    int b = z >> 3, h = z & 7;
    const float* base = g_qkv + ((size_t)(b * MTOK + m)) * (3 * CC) + h * DH + d;
    g_q[gid] = base[0] * 0.125f;
    g_k[gid] = base[CC];
    g_v[gid] = base[2 * CC];
}

// ---------------- softmax + fused attn@xyz ----------------
__global__ void softmax_kernel() {
    int blk = blockIdx.x;                 // z*1024 + i
    int z = blk >> 10, i = blk & (MTOK - 1);
    int b = z >> 3;
    (void)i;
    float* p = g_attn + (size_t)blk * MTOK;
    int tid = threadIdx.x;                // 256
    float v0 = p[tid], v1 = p[tid + 256], v2 = p[tid + 512], v3 = p[tid + 768];
    float mx = fmaxf(fmaxf(v0, v1), fmaxf(v2, v3));
    __shared__ float red[8];
    #pragma unroll
    for (int o = 16; o; o >>= 1) mx = fmaxf(mx, __shfl_xor_sync(0xffffffffu, mx, o));
    if ((tid & 31) == 0) red[tid >> 5] = mx;
    __syncthreads();
    if (tid == 0) {
        float m = red[0];
        #pragma unroll
        for (int q = 1; q < 8; q++) m = fmaxf(m, red[q]);
        red[0] = m;
    }
    __syncthreads();
    mx = red[0];
    __syncthreads();
    float e0 = expf(v0 - mx), e1 = expf(v1 - mx), e2 = expf(v2 - mx), e3 = expf(v3 - mx);
    float s = ((e0 + e1) + e2) + e3;
    #pragma unroll
    for (int o = 16; o; o >>= 1) s += __shfl_xor_sync(0xffffffffu, s, o);
    if ((tid & 31) == 0) red[tid >> 5] = s;
    __syncthreads();
    if (tid == 0) {
        float m = 0.f;
        #pragma unroll
        for (int q = 0; q < 8; q++) m += red[q];
        red[0] = m;
    }
    __syncthreads();
    float inv = 1.0f / red[0];
    float p0 = e0 * inv, p1 = e1 * inv, p2 = e2 * inv, p3 = e3 * inv;
    p[tid] = p0; p[tid + 256] = p1; p[tid + 512] = p2; p[tid + 768] = p3;

    // fused attn @ xyz
    const float* xyzb = g_anchor + (size_t)b * MTOK * 3;
    float s0 = p0 * xyzb[tid * 3 + 0] + p1 * xyzb[(tid + 256) * 3 + 0]
             + p2 * xyzb[(tid + 512) * 3 + 0] + p3 * xyzb[(tid + 768) * 3 + 0];
    float s1 = p0 * xyzb[tid * 3 + 1] + p1 * xyzb[(tid + 256) * 3 + 1]
             + p2 * xyzb[(tid + 512) * 3 + 1] + p3 * xyzb[(tid + 768) * 3 + 1];
    float s2 = p0 * xyzb[tid * 3 + 2] + p1 * xyzb[(tid + 256) * 3 + 2]
             + p2 * xyzb[(tid + 512) * 3 + 2] + p3 * xyzb[(tid + 768) * 3 + 2];
    __shared__ float sr0[8], sr1[8], sr2[8];
    #pragma unroll
    for (int o = 16; o; o >>= 1) {
        s0 += __shfl_xor_sync(0xffffffffu, s0, o);
        s1 += __shfl_xor_sync(0xffffffffu, s1, o);
        s2 += __shfl_xor_sync(0xffffffffu, s2, o);
    }
    if ((tid & 31) == 0) { sr0[tid >> 5] = s0; sr1[tid >> 5] = s1; sr2[tid >> 5] = s2; }
    __syncthreads();
    if (tid == 0) {
        float a0 = 0, a1 = 0, a2 = 0;
        #pragma unroll
        for (int q = 0; q < 8; q++) { a0 += sr0[q]; a1 += sr1[q]; a2 += sr2[q]; }
        g_axyz[(size_t)blk * 3 + 0] = a0;
        g_axyz[(size_t)blk * 3 + 1] = a1;
        g_axyz[(size_t)blk * 3 + 2] = a2;
    }
}

// ---------------- combine out_v + spatial displacement projection ----------------
__global__ void combine_kernel(const float* __restrict__ Wsp) {
    int gid = blockIdx.x * blockDim.x + threadIdx.x;
    if (gid >= BB * MTOK * CC) return;
    int d = gid & 63;
    int h = (gid >> 6) & 7;
    int i = (gid >> 9) & (MTOK - 1);
    int b = gid >> 19;
    int z = b * 8 + h;
    float v = g_ov[((size_t)z * MTOK + i) * DH + d];
    const float* ax = g_axyz + ((size_t)z * MTOK + i) * 3;
    const float* xy = g_anchor + ((size_t)b * MTOK + i) * 3;
    float w0 = Wsp[d * 3 + 0], w1 = Wsp[d * 3 + 1], w2 = Wsp[d * 3 + 2];
    v += (ax[0] - xy[0]) * w0 + (ax[1] - xy[1]) * w1 + (ax[2] - xy[2]) * w2;
    g_attnout[((size_t)b * MTOK + i) * CC + h * DH + d] = v;
}

// ---------------- launch ----------------
extern "C" void kernel_launch(void* const* d_in, const int* in_sizes, int n_in,
                              void* d_out, int out_size) {
    const float* xyzs  = (const float*)d_in[0];
    const float* Wd    = (const float*)d_in[1];
    const float* Wqkv  = (const float*)d_in[2];
    const float* Wsp   = (const float*)d_in[3];
    const float* Wout  = (const float*)d_in[4];
    const float* bout  = (const float*)d_in[5];
    const float* ln1g  = (const float*)d_in[6];
    const float* ln1b  = (const float*)d_in[7];
    const float* Wff1  = (const float*)d_in[8];
    const float* bff1  = (const float*)d_in[9];
    const float* Wff2  = (const float*)d_in[10];
    const float* bff2  = (const float*)d_in[11];
    const float* ln2g  = (const float*)d_in[12];
    const float* ln2b  = (const float*)d_in[13];
    float* outp = (float*)d_out;

    float *p_feats, *p_xln, *p_qkv, *p_q, *p_k, *p_v, *p_ov, *p_attn, *p_ao, *p_hid;
    cudaGetSymbolAddress((void**)&p_feats, g_feats);
    cudaGetSymbolAddress((void**)&p_xln, g_xln);
    cudaGetSymbolAddress((void**)&p_qkv, g_qkv);
    cudaGetSymbolAddress((void**)&p_q, g_q);
    cudaGetSymbolAddress((void**)&p_k, g_k);
    cudaGetSymbolAddress((void**)&p_v, g_v);
    cudaGetSymbolAddress((void**)&p_ov, g_ov);
    cudaGetSymbolAddress((void**)&p_attn, g_attn);
    cudaGetSymbolAddress((void**)&p_ao, g_attnout);
    cudaGetSymbolAddress((void**)&p_hid, g_hid);

    fps_kernel<<<BB * TT, 1024>>>(xyzs);
    ballq_kernel<<<(BB * TT * 3 * MM + 255) / 256, 256>>>(xyzs);
    conv_kernel<<<BB * TT * MM, CC>>>(xyzs, Wd);

    for (int dep = 0; dep < 2; dep++) {
        const float* Wqkv_d = Wqkv + (size_t)dep * 3 * CC * CC;
        const float* Wsp_d  = Wsp  + (size_t)dep * DH * 3;
        const float* Wout_d = Wout + (size_t)dep * CC * CC;
        const float* bout_d = bout + (size_t)dep * CC;
        const float* l1g = ln1g + dep * CC, *l1b = ln1b + dep * CC;
        const float* Wff1_d = Wff1 + (size_t)dep * MLPD * CC;
        const float* bff1_d = bff1 + (size_t)dep * MLPD;
        const float* Wff2_d = Wff2 + (size_t)dep * CC * MLPD;
        const float* bff2_d = bff2 + (size_t)dep * CC;
        const float* l2g = ln2g + dep * CC, *l2b = ln2b + dep * CC;

        // LN1 + QKV  (M=2048, N=1536, K=512)
        ln_kernel<<<BB * MTOK, CC>>>(p_feats, p_xln, l1g, l1b);
        gemm_k<128, 128, 16, 8, 8, 1><<<dim3(1536 / 128, 2048 / 128, 1), 256>>>(
            p_xln, Wqkv_d, p_qkv, CC, 3 * CC, nullptr, 0, nullptr, 0, 0, 0);
        split_kernel<<<(NBH * MTOK * DH + 255) / 256, 256>>>();

        // dots = Q @ K^T  (16 x [1024,1024,64])
        gemm_k<128, 128, 16, 8, 8, 1><<<dim3(8, 8, NBH), 256>>>(
            p_q, p_k, p_attn, DH, MTOK, nullptr, 0, nullptr,
            (long long)MTOK * DH, (long long)MTOK * DH, (long long)MTOK * MTOK);
        softmax_kernel<<<NBH * MTOK, 256>>>();

        // out_v = attn @ V  (16 x [1024,64,1024])
        gemm_k<128, 64, 16, 8, 4, 0><<<dim3(1, 8, NBH), 256>>>(
            p_attn, p_v, p_ov, MTOK, DH, nullptr, 0, nullptr,
            (long long)MTOK * MTOK, (long long)MTOK * DH, (long long)MTOK * DH);

        combine_kernel<<<(BB * MTOK * CC + 255) / 256, 256>>>(Wsp_d);

        // out projection + bias + gelu + residual  (M=2048, N=512, K=512)
        gemm_k<128, 64, 16, 8, 4, 1><<<dim3(512 / 64, 2048 / 128, 1), 256>>>(
            p_ao, Wout_d, p_feats, CC, CC, bout_d, 1, p_feats, 0, 0, 0);

        // FF
        ln_kernel<<<BB * MTOK, CC>>>(p_feats, p_xln, l2g, l2b);
        gemm_k<128, 128, 16, 8, 8, 1><<<dim3(MLPD / 128, 2048 / 128, 1), 256>>>(
            p_xln, Wff1_d, p_hid, CC, MLPD, bff1_d, 1, nullptr, 0, 0, 0);
        float* cdst = (dep == 1) ? outp : p_feats;
        gemm_k<128, 64, 16, 8, 4, 1><<<dim3(512 / 64, 2048 / 128, 1), 256>>>(
            p_hid, Wff2_d, cdst, MLPD, CC, bff2_d, 0, p_feats, 0, 0, 0);
    }
}